// round 2
// baseline (speedup 1.0000x reference)
#include <cuda_runtime.h>
#include <math.h>

typedef unsigned long long ull;

#define NB 16
#define NS 512
#define NH 16
#define ND 64
#define NHID 1024
#define NROW (NB*NS)        // 8192
#define NBH (NB*NH)         // 256
#define NTOK (NBH*NS*ND)    // 8388608

// ---------------- scratch (static __device__, allocation-guard safe) ----------------
__device__ __align__(16) float g_proj[2][NROW*NHID];
__device__ __align__(16) float g_c[2][NTOK];           // (B,H,S,D)
__device__ __align__(16) float g_q[2][NTOK];
__device__ __align__(16) float g_k[2][NTOK];
__device__ __align__(16) float g_v[2][NTOK];
__device__ __align__(16) float g_o[2][NTOK];
__device__ __align__(16) float g_comb[NBH*NS*2*ND];    // (B,H,S,128)

// ---------------- packed f32x2 helpers (sm_100+ FFMA2) ----------------
__device__ __forceinline__ void ffma2(ull& d, ull a, ull b) {
    asm("fma.rn.f32x2 %0, %1, %2, %0;" : "+l"(d) : "l"(a), "l"(b));
}
__device__ __forceinline__ ull fmul2(ull a, ull b) {
    ull r; asm("mul.rn.f32x2 %0, %1, %2;" : "=l"(r) : "l"(a), "l"(b)); return r;
}
__device__ __forceinline__ ull pack2(float x, float y) {
    ull r; asm("mov.b64 %0, {%1, %2};" : "=l"(r) : "f"(x), "f"(y)); return r;
}
__device__ __forceinline__ float2 unpack2(ull v) {
    float2 f; asm("mov.b64 {%0, %1}, %2;" : "=f"(f.x), "=f"(f.y) : "l"(v)); return f;
}

// ---------------- big projection GEMM: C[M,1024] = A[M,K] @ W[1024,K]^T + bias ------
__global__ void gemm_bias_kernel(const float* __restrict__ A,
                                 const float* __restrict__ W,
                                 const float* __restrict__ bias,
                                 int K, int which) {
    __shared__ __align__(16) float2 As2[16][64];   // duplicated {a,a}
    __shared__ __align__(16) float  Ws[16][64];
    float* C = g_proj[which];
    const int N = NHID;
    int tid = threadIdx.x;
    int tx4 = (tid & 15) * 4, ty4 = (tid >> 4) * 4;
    int m0 = blockIdx.y * 64, n0 = blockIdx.x * 64;
    int lrow = tid >> 2;
    int lk = (tid & 3) * 4;
    ull acc[4][2] = {};
    for (int k0 = 0; k0 < K; k0 += 16) {
        float4 av = *(const float4*)(A + (size_t)(m0 + lrow) * K + k0 + lk);
        float4 wv = *(const float4*)(W + (size_t)(n0 + lrow) * K + k0 + lk);
        As2[lk+0][lrow] = make_float2(av.x, av.x);
        As2[lk+1][lrow] = make_float2(av.y, av.y);
        As2[lk+2][lrow] = make_float2(av.z, av.z);
        As2[lk+3][lrow] = make_float2(av.w, av.w);
        Ws[lk+0][lrow]=wv.x; Ws[lk+1][lrow]=wv.y; Ws[lk+2][lrow]=wv.z; Ws[lk+3][lrow]=wv.w;
        __syncthreads();
        #pragma unroll
        for (int kk = 0; kk < 16; kk++) {
            ulonglong2 aA = *(const ulonglong2*)&As2[kk][ty4];
            ulonglong2 aB = *(const ulonglong2*)&As2[kk][ty4+2];
            ulonglong2 wp = *(const ulonglong2*)&Ws[kk][tx4];
            ffma2(acc[0][0], aA.x, wp.x); ffma2(acc[0][1], aA.x, wp.y);
            ffma2(acc[1][0], aA.y, wp.x); ffma2(acc[1][1], aA.y, wp.y);
            ffma2(acc[2][0], aB.x, wp.x); ffma2(acc[2][1], aB.x, wp.y);
            ffma2(acc[3][0], aB.y, wp.x); ffma2(acc[3][1], aB.y, wp.y);
        }
        __syncthreads();
    }
    #pragma unroll
    for (int i=0;i<4;i++) {
        int m = m0 + ty4 + i;
        int n = n0 + tx4;
        float2 f0 = unpack2(acc[i][0]), f1 = unpack2(acc[i][1]);
        C[(size_t)m*N + n+0] = f0.x + bias[n+0];
        C[(size_t)m*N + n+1] = f0.y + bias[n+1];
        C[(size_t)m*N + n+2] = f1.x + bias[n+2];
        C[(size_t)m*N + n+3] = f1.y + bias[n+3];
    }
}

// ---------------- LN + l2-normalize + D^-0.5, writes (B,H,S,D) layout ----------------
__device__ __forceinline__ float breduce256(float v, float* red) {
    #pragma unroll
    for (int o = 16; o > 0; o >>= 1) v += __shfl_xor_sync(0xffffffffu, v, o);
    int tid = threadIdx.x;
    if ((tid & 31) == 0) red[tid >> 5] = v;
    __syncthreads();
    float t = 0.f;
    #pragma unroll
    for (int i = 0; i < 8; i++) t += red[i];
    __syncthreads();
    return t;
}

__global__ void ln_l2_kernel(const float* __restrict__ g, const float* __restrict__ b, int which) {
    __shared__ float red[8];
    int row = blockIdx.x;
    int tid = threadIdx.x;
    const float* y = g_proj[which] + (size_t)row * NHID;
    float v[4], sum = 0.f;
    #pragma unroll
    for (int i=0;i<4;i++){ v[i] = y[tid + i*256]; sum += v[i]; }
    sum = breduce256(sum, red);
    float mu = sum * (1.f/NHID);
    float sq = 0.f;
    #pragma unroll
    for (int i=0;i<4;i++){ float d = v[i]-mu; sq += d*d; }
    sq = breduce256(sq, red);
    float rstd = rsqrtf(sq*(1.f/NHID) + 1e-5f);
    float ln[4], s2 = 0.f;
    #pragma unroll
    for (int i=0;i<4;i++){ int n = tid+i*256; ln[i] = (v[i]-mu)*rstd*g[n] + b[n]; s2 += ln[i]*ln[i]; }
    s2 = breduce256(s2, red);
    float scale = 0.125f / fmaxf(sqrtf(s2), 1e-12f);
    int bb = row >> 9, s = row & 511;
    float* outp = g_c[which];
    #pragma unroll
    for (int i=0;i<4;i++){
        int n = tid + i*256;
        int h = n >> 6, d = n & 63;
        outp[(((size_t)(bb*NH + h))*NS + s)*ND + d] = ln[i]*scale;
    }
}

// ---------------- per-head QKV projection ----------------
__global__ void qkv_kernel(const float* __restrict__ in_w, const float* __restrict__ in_b, int which) {
    __shared__ __align__(16) float2 X2[64][64];   // [d][s] duplicated
    __shared__ __align__(16) float  Ws[64][64];   // [d][e]
    const float* qsrc  = g_c[which];
    const float* kvsrc = g_c[which ^ 1];
    int bh = blockIdx.y;
    int h = bh & (NH-1);
    int s0 = blockIdx.x * 64;
    int tid = threadIdx.x, tx4 = (tid & 15)*4, ty4 = (tid >> 4)*4;
    int lrow = tid >> 2;
    const float* qbase  = qsrc  + ((size_t)bh*NS + s0)*ND;
    const float* kvbase = kvsrc + ((size_t)bh*NS + s0)*ND;
    for (int p = 0; p < 3; p++) {
        if (p < 2) {
            const float* src = (p == 0) ? qbase : kvbase;
            #pragma unroll
            for (int it = 0; it < 4; it++) {
                int c = ((tid & 3) + it*4) * 4;
                float4 a = *(const float4*)(src + lrow*64 + c);
                X2[c+0][lrow] = make_float2(a.x, a.x);
                X2[c+1][lrow] = make_float2(a.y, a.y);
                X2[c+2][lrow] = make_float2(a.z, a.z);
                X2[c+3][lrow] = make_float2(a.w, a.w);
            }
        }
        const float* wsrc = in_w + ((size_t)h*192 + p*64)*64;   // W[e][d]
        #pragma unroll
        for (int it = 0; it < 4; it++) {
            int c = ((tid & 3) + it*4) * 4;
            float4 w = *(const float4*)(wsrc + lrow*64 + c);
            Ws[c+0][lrow]=w.x; Ws[c+1][lrow]=w.y; Ws[c+2][lrow]=w.z; Ws[c+3][lrow]=w.w;
        }
        __syncthreads();
        ull acc[4][2] = {};
        #pragma unroll 8
        for (int d = 0; d < 64; d++) {
            ulonglong2 aA = *(const ulonglong2*)&X2[d][ty4];
            ulonglong2 aB = *(const ulonglong2*)&X2[d][ty4+2];
            ulonglong2 wp = *(const ulonglong2*)&Ws[d][tx4];
            ffma2(acc[0][0], aA.x, wp.x); ffma2(acc[0][1], aA.x, wp.y);
            ffma2(acc[1][0], aA.y, wp.x); ffma2(acc[1][1], aA.y, wp.y);
            ffma2(acc[2][0], aB.x, wp.x); ffma2(acc[2][1], aB.x, wp.y);
            ffma2(acc[3][0], aB.y, wp.x); ffma2(acc[3][1], aB.y, wp.y);
        }
        float* dst = (p==0) ? g_q[which] : (p==1) ? g_k[which] : g_v[which];
        float qscale = (p==0) ? 0.125f : 1.f;
        const float* bsrc = in_b + h*192 + p*64;
        #pragma unroll
        for (int i=0;i<4;i++){
            int s = s0 + ty4 + i;
            float2 f0 = unpack2(acc[i][0]), f1 = unpack2(acc[i][1]);
            float* drow = dst + ((size_t)bh*NS + s)*ND + tx4;
            drow[0] = (f0.x + bsrc[tx4+0]) * qscale;
            drow[1] = (f0.y + bsrc[tx4+1]) * qscale;
            drow[2] = (f1.x + bsrc[tx4+2]) * qscale;
            drow[3] = (f1.y + bsrc[tx4+3]) * qscale;
        }
        __syncthreads();
    }
}

// ---------------- flash-style attention, 64-query tile, packed f32x2 ----------------
__global__ void attn_kernel(int which) {
    extern __shared__ __align__(16) char smraw[];
    float2 (*qsd)[64] = (float2(*)[64])smraw;                  // [d][i] dup, 32768 B
    float  (*ks)[64]  = (float(*)[64])(smraw + 32768);         // [d][j], 16384 B
    float  (*vs)[64]  = (float(*)[64])(smraw + 49152);         // [j][e], 16384 B
    float2 (*psT)[66] = (float2(*)[66])(smraw + 65536);        // [j][i] dup, 33792 B
    float* rowm = (float*)(smraw + 65536 + 33792);
    float* rowl = rowm + 64;
    float* rowf = rowl + 64;
    const float* Q = g_q[which];
    const float* K = g_k[which];
    const float* V = g_v[which];
    float* O = g_o[which];
    int bh = blockIdx.y, q0 = blockIdx.x * 64;
    int tid = threadIdx.x, tx4 = (tid & 15)*4, ty4 = (tid >> 4)*4;
    int lrow = tid >> 2;
    const float* qbase = Q + ((size_t)bh*NS + q0)*ND;
    #pragma unroll
    for (int it = 0; it < 4; it++) {
        int c = ((tid & 3) + it*4) * 4;
        float4 a = *(const float4*)(qbase + lrow*64 + c);
        qsd[c+0][lrow] = make_float2(a.x, a.x);
        qsd[c+1][lrow] = make_float2(a.y, a.y);
        qsd[c+2][lrow] = make_float2(a.z, a.z);
        qsd[c+3][lrow] = make_float2(a.w, a.w);
    }
    if (tid < 64) { rowm[tid] = -1e30f; rowl[tid] = 0.f; }
    ull o[4][2] = {};
    __syncthreads();
    for (int j0 = 0; j0 < NS; j0 += 64) {
        const float* kbase = K + ((size_t)bh*NS + j0)*ND;
        const float* vbase = V + ((size_t)bh*NS + j0)*ND;
        #pragma unroll
        for (int it = 0; it < 4; it++) {
            int c = ((tid & 3) + it*4) * 4;
            float4 kk = *(const float4*)(kbase + lrow*64 + c);
            ks[c+0][lrow]=kk.x; ks[c+1][lrow]=kk.y; ks[c+2][lrow]=kk.z; ks[c+3][lrow]=kk.w;
            ((float4*)vs)[tid + it*256] = ((const float4*)vbase)[tid + it*256];
        }
        __syncthreads();
        // ---- QK^T ----
        ull sc[4][2] = {};
        #pragma unroll 8
        for (int d = 0; d < 64; d++) {
            ulonglong2 aA = *(const ulonglong2*)&qsd[d][ty4];
            ulonglong2 aB = *(const ulonglong2*)&qsd[d][ty4+2];
            ulonglong2 kp = *(const ulonglong2*)&ks[d][tx4];
            ffma2(sc[0][0], aA.x, kp.x); ffma2(sc[0][1], aA.x, kp.y);
            ffma2(sc[1][0], aA.y, kp.x); ffma2(sc[1][1], aA.y, kp.y);
            ffma2(sc[2][0], aB.x, kp.x); ffma2(sc[2][1], aB.x, kp.y);
            ffma2(sc[3][0], aB.y, kp.x); ffma2(sc[3][1], aB.y, kp.y);
        }
        #pragma unroll
        for (int i=0;i<4;i++){
            float2 f0 = unpack2(sc[i][0]), f1 = unpack2(sc[i][1]);
            psT[tx4+0][ty4+i].x = f0.x;
            psT[tx4+1][ty4+i].x = f0.y;
            psT[tx4+2][ty4+i].x = f1.x;
            psT[tx4+3][ty4+i].x = f1.y;
        }
        __syncthreads();
        // ---- online softmax (rows = queries) ----
        if (tid < 64) {
            float mold = rowm[tid];
            float mx = mold;
            #pragma unroll 8
            for (int j=0;j<64;j++) mx = fmaxf(mx, psT[j][tid].x);
            float f = __expf(mold - mx);
            float l = 0.f;
            #pragma unroll 8
            for (int j=0;j<64;j++){
                float e = __expf(psT[j][tid].x - mx);
                psT[j][tid] = make_float2(e, e);
                l += e;
            }
            rowl[tid] = rowl[tid]*f + l;
            rowm[tid] = mx;
            rowf[tid] = f;
        }
        __syncthreads();
        // ---- rescale + PV ----
        #pragma unroll
        for (int i=0;i<4;i++){
            ull fd = pack2(rowf[ty4+i], rowf[ty4+i]);
            o[i][0] = fmul2(o[i][0], fd);
            o[i][1] = fmul2(o[i][1], fd);
        }
        #pragma unroll 8
        for (int j=0;j<64;j++){
            ulonglong2 pA = *(const ulonglong2*)&psT[j][ty4];
            ulonglong2 pB = *(const ulonglong2*)&psT[j][ty4+2];
            ulonglong2 vp = *(const ulonglong2*)&vs[j][tx4];
            ffma2(o[0][0], pA.x, vp.x); ffma2(o[0][1], pA.x, vp.y);
            ffma2(o[1][0], pA.y, vp.x); ffma2(o[1][1], pA.y, vp.y);
            ffma2(o[2][0], pB.x, vp.x); ffma2(o[2][1], pB.x, vp.y);
            ffma2(o[3][0], pB.y, vp.x); ffma2(o[3][1], pB.y, vp.y);
        }
        __syncthreads();
    }
    #pragma unroll
    for (int i=0;i<4;i++){
        float il = 1.f / rowl[ty4+i];
        float2 f0 = unpack2(o[i][0]), f1 = unpack2(o[i][1]);
        float* orow = O + ((size_t)bh*NS + q0 + ty4+i)*ND + tx4;
        orow[0] = f0.x * il;
        orow[1] = f0.y * il;
        orow[2] = f1.x * il;
        orow[3] = f1.y * il;
    }
}

// ---------------- out projection + residual ----------------
__global__ void outproj_kernel(const float* __restrict__ out_w, const float* __restrict__ out_b, int which) {
    __shared__ __align__(16) float2 X2[64][64];   // [e][s] dup
    __shared__ __align__(16) float  Ws[64][64];   // [e][f]
    const float* Oin   = g_o[which];
    const float* resid = g_c[which];
    int bh = blockIdx.y, h = bh & (NH-1), s0 = blockIdx.x*64;
    int tid = threadIdx.x, tx4 = (tid&15)*4, ty4 = (tid>>4)*4, lrow = tid>>2;
    const float* xbase = Oin + ((size_t)bh*NS + s0)*ND;
    const float* wsrc  = out_w + (size_t)h*64*64;       // W[f][e]
    #pragma unroll
    for (int it=0; it<4; it++){
        int c = ((tid&3)+it*4)*4;
        float4 x = *(const float4*)(xbase + lrow*64 + c);
        float4 w = *(const float4*)(wsrc  + lrow*64 + c);
        X2[c+0][lrow]=make_float2(x.x,x.x);
        X2[c+1][lrow]=make_float2(x.y,x.y);
        X2[c+2][lrow]=make_float2(x.z,x.z);
        X2[c+3][lrow]=make_float2(x.w,x.w);
        Ws[c+0][lrow]=w.x; Ws[c+1][lrow]=w.y; Ws[c+2][lrow]=w.z; Ws[c+3][lrow]=w.w;
    }
    __syncthreads();
    ull acc[4][2] = {};
    #pragma unroll 8
    for (int e = 0; e < 64; e++) {
        ulonglong2 aA = *(const ulonglong2*)&X2[e][ty4];
        ulonglong2 aB = *(const ulonglong2*)&X2[e][ty4+2];
        ulonglong2 wp = *(const ulonglong2*)&Ws[e][tx4];
        ffma2(acc[0][0], aA.x, wp.x); ffma2(acc[0][1], aA.x, wp.y);
        ffma2(acc[1][0], aA.y, wp.x); ffma2(acc[1][1], aA.y, wp.y);
        ffma2(acc[2][0], aB.x, wp.x); ffma2(acc[2][1], aB.x, wp.y);
        ffma2(acc[3][0], aB.y, wp.x); ffma2(acc[3][1], aB.y, wp.y);
    }
    int off = which * 64;
    #pragma unroll
    for (int i=0;i<4;i++){
        int s = s0 + ty4 + i;
        float2 f0 = unpack2(acc[i][0]), f1 = unpack2(acc[i][1]);
        const float* rrow = resid + ((size_t)bh*NS+s)*ND + tx4;
        float* drow = g_comb + ((size_t)bh*NS + s)*128 + off + tx4;
        drow[0] = f0.x + out_b[h*64+tx4+0] + rrow[0];
        drow[1] = f0.y + out_b[h*64+tx4+1] + rrow[1];
        drow[2] = f1.x + out_b[h*64+tx4+2] + rrow[2];
        drow[3] = f1.y + out_b[h*64+tx4+3] + rrow[3];
    }
}

// ---------------- final LN over concat dim (128) ----------------
__global__ void final_ln_kernel(const float* __restrict__ hg, const float* __restrict__ hb,
                                float* __restrict__ out) {
    int row = blockIdx.x * 8 + (threadIdx.x >> 5);
    int lane = threadIdx.x & 31;
    const float* x = g_comb + (size_t)row * 128;
    float v[4], sum = 0.f;
    #pragma unroll
    for (int i=0;i<4;i++){ v[i] = x[lane + i*32]; sum += v[i]; }
    #pragma unroll
    for (int o = 16; o > 0; o >>= 1) sum += __shfl_xor_sync(0xffffffffu, sum, o);
    float mu = sum * (1.f/128.f);
    float sq = 0.f;
    #pragma unroll
    for (int i=0;i<4;i++){ float d = v[i]-mu; sq += d*d; }
    #pragma unroll
    for (int o = 16; o > 0; o >>= 1) sq += __shfl_xor_sync(0xffffffffu, sq, o);
    float rstd = rsqrtf(sq*(1.f/128.f) + 1e-5f);
    int h = (row >> 9) & 15;
    #pragma unroll
    for (int i=0;i<4;i++){
        int c = lane + i*32;
        out[(size_t)row*128 + c] = (v[i]-mu)*rstd*hg[h*128+c] + hb[h*128+c];
    }
}

// ---------------- launch ----------------
extern "C" void kernel_launch(void* const* d_in, const int* in_sizes, int n_in,
                              void* d_out, int out_size) {
    const float* image     = (const float*)d_in[0];
    const float* text      = (const float*)d_in[1];
    const float* img_w     = (const float*)d_in[2];
    const float* img_b     = (const float*)d_in[3];
    const float* img_g     = (const float*)d_in[4];
    const float* img_lb    = (const float*)d_in[5];
    const float* txt_w     = (const float*)d_in[6];
    const float* txt_b     = (const float*)d_in[7];
    const float* txt_g     = (const float*)d_in[8];
    const float* txt_lb    = (const float*)d_in[9];
    const float* i2t_in_w  = (const float*)d_in[10];
    const float* i2t_in_b  = (const float*)d_in[11];
    const float* i2t_out_w = (const float*)d_in[12];
    const float* i2t_out_b = (const float*)d_in[13];
    const float* t2i_in_w  = (const float*)d_in[14];
    const float* t2i_in_b  = (const float*)d_in[15];
    const float* t2i_out_w = (const float*)d_in[16];
    const float* t2i_out_b = (const float*)d_in[17];
    const float* hn_g      = (const float*)d_in[18];
    const float* hn_b      = (const float*)d_in[19];
    float* out = (float*)d_out;

    static int attn_smem_set = 0;
    const int ATTN_SMEM = 65536 + 33792 + 3*256;
    if (!attn_smem_set) {
        cudaFuncSetAttribute(attn_kernel, cudaFuncAttributeMaxDynamicSharedMemorySize, ATTN_SMEM);
        attn_smem_set = 1;
    }

    dim3 thr(256);
    gemm_bias_kernel<<<dim3(16,128), thr>>>(image, img_w, img_b, 768, 0);
    gemm_bias_kernel<<<dim3(16,128), thr>>>(text,  txt_w, txt_b, 512, 1);
    ln_l2_kernel<<<8192, thr>>>(img_g, img_lb, 0);
    ln_l2_kernel<<<8192, thr>>>(txt_g, txt_lb, 1);
    qkv_kernel<<<dim3(8,256), thr>>>(i2t_in_w, i2t_in_b, 0);
    qkv_kernel<<<dim3(8,256), thr>>>(t2i_in_w, t2i_in_b, 1);
    attn_kernel<<<dim3(8,256), thr, ATTN_SMEM>>>(0);
    attn_kernel<<<dim3(8,256), thr, ATTN_SMEM>>>(1);
    outproj_kernel<<<dim3(8,256), thr>>>(i2t_out_w, i2t_out_b, 0);
    outproj_kernel<<<dim3(8,256), thr>>>(t2i_out_w, t2i_out_b, 1);
    final_ln_kernel<<<16384, thr>>>(hn_g, hn_b, out);
}

// round 3
// speedup vs baseline: 1.6074x; 1.6074x over previous
#include <cuda_runtime.h>
#include <math.h>

#define NB 16
#define NS 512
#define NH 16
#define ND 64
#define NHID 1024
#define NROW (NB*NS)        // 8192
#define NBH (NB*NH)         // 256
#define NTOK (NBH*NS*ND)    // 8388608

// ---------------- scratch (static __device__, allocation-guard safe) ----------------
__device__ __align__(16) float g_proj[2][NROW*NHID];
__device__ __align__(16) float g_c[2][NTOK];           // (B,H,S,D)
__device__ __align__(16) float g_q[2][NTOK];
__device__ __align__(16) float g_k[2][NTOK];
__device__ __align__(16) float g_v[2][NTOK];
__device__ __align__(16) float g_o[2][NTOK];
__device__ __align__(16) float g_comb[NBH*NS*2*ND];    // (B,H,S,128)

// ---------------- tf32 mma helpers ----------------
__device__ __forceinline__ unsigned cvt_tf32(float x) {
    unsigned u; asm("cvt.rna.tf32.f32 %0, %1;" : "=r"(u) : "f"(x)); return u;
}
__device__ __forceinline__ float tf32f(float x) {
    return __uint_as_float(cvt_tf32(x));
}
__device__ __forceinline__ void mma_tf32(float c[4], const unsigned a[4], unsigned b0, unsigned b1) {
    asm("mma.sync.aligned.m16n8k8.row.col.f32.tf32.tf32.f32 "
        "{%0,%1,%2,%3}, {%4,%5,%6,%7}, {%8,%9}, {%0,%1,%2,%3};"
        : "+f"(c[0]), "+f"(c[1]), "+f"(c[2]), "+f"(c[3])
        : "r"(a[0]), "r"(a[1]), "r"(a[2]), "r"(a[3]), "r"(b0), "r"(b1));
}

// ---------------- big projection GEMM: C[M,1024] = A[M,K] @ W[1024,K]^T + bias ------
__global__ void gemm_bias_kernel(const float* __restrict__ A,
                                 const float* __restrict__ W,
                                 const float* __restrict__ bias,
                                 int K, int which) {
    __shared__ __align__(16) float As[16][64];
    __shared__ __align__(16) float Ws[16][64];
    float* C = g_proj[which];
    const int N = NHID;
    int tid = threadIdx.x;
    int tx = tid & 15, ty = tid >> 4;
    int m0 = blockIdx.y * 64, n0 = blockIdx.x * 64;
    int lrow = tid >> 2;
    int lk = (tid & 3) * 4;
    float acc[4][4] = {};
    for (int k0 = 0; k0 < K; k0 += 16) {
        float4 av = *(const float4*)(A + (size_t)(m0 + lrow) * K + k0 + lk);
        float4 wv = *(const float4*)(W + (size_t)(n0 + lrow) * K + k0 + lk);
        As[lk+0][lrow]=av.x; As[lk+1][lrow]=av.y; As[lk+2][lrow]=av.z; As[lk+3][lrow]=av.w;
        Ws[lk+0][lrow]=wv.x; Ws[lk+1][lrow]=wv.y; Ws[lk+2][lrow]=wv.z; Ws[lk+3][lrow]=wv.w;
        __syncthreads();
        #pragma unroll
        for (int kk = 0; kk < 16; kk++) {
            float4 a4 = *(const float4*)(&As[kk][ty*4]);
            float4 w4 = *(const float4*)(&Ws[kk][tx*4]);
            float a[4] = {a4.x, a4.y, a4.z, a4.w};
            float w[4] = {w4.x, w4.y, w4.z, w4.w};
            #pragma unroll
            for (int i=0;i<4;i++)
                #pragma unroll
                for (int j=0;j<4;j++) acc[i][j] = fmaf(a[i], w[j], acc[i][j]);
        }
        __syncthreads();
    }
    #pragma unroll
    for (int i=0;i<4;i++) {
        int m = m0 + ty*4 + i;
        #pragma unroll
        for (int j=0;j<4;j++) {
            int n = n0 + tx*4 + j;
            C[(size_t)m*N + n] = acc[i][j] + bias[n];
        }
    }
}

// ---------------- LN + l2-normalize + D^-0.5, writes (B,H,S,D) layout ----------------
__device__ __forceinline__ float breduce256(float v, float* red) {
    #pragma unroll
    for (int o = 16; o > 0; o >>= 1) v += __shfl_xor_sync(0xffffffffu, v, o);
    int tid = threadIdx.x;
    if ((tid & 31) == 0) red[tid >> 5] = v;
    __syncthreads();
    float t = 0.f;
    #pragma unroll
    for (int i = 0; i < 8; i++) t += red[i];
    __syncthreads();
    return t;
}

__global__ void ln_l2_kernel(const float* __restrict__ g, const float* __restrict__ b, int which) {
    __shared__ float red[8];
    int row = blockIdx.x;
    int tid = threadIdx.x;
    const float* y = g_proj[which] + (size_t)row * NHID;
    float v[4], sum = 0.f;
    #pragma unroll
    for (int i=0;i<4;i++){ v[i] = y[tid + i*256]; sum += v[i]; }
    sum = breduce256(sum, red);
    float mu = sum * (1.f/NHID);
    float sq = 0.f;
    #pragma unroll
    for (int i=0;i<4;i++){ float d = v[i]-mu; sq += d*d; }
    sq = breduce256(sq, red);
    float rstd = rsqrtf(sq*(1.f/NHID) + 1e-5f);
    float ln[4], s2 = 0.f;
    #pragma unroll
    for (int i=0;i<4;i++){ int n = tid+i*256; ln[i] = (v[i]-mu)*rstd*g[n] + b[n]; s2 += ln[i]*ln[i]; }
    s2 = breduce256(s2, red);
    float scale = 0.125f / fmaxf(sqrtf(s2), 1e-12f);
    int bb = row >> 9, s = row & 511;
    float* outp = g_c[which];
    #pragma unroll
    for (int i=0;i<4;i++){
        int n = tid + i*256;
        int h = n >> 6, d = n & 63;
        outp[(((size_t)(bb*NH + h))*NS + s)*ND + d] = ln[i]*scale;
    }
}

// ---------------- per-head QKV projection ----------------
__global__ void qkv_kernel(const float* __restrict__ in_w, const float* __restrict__ in_b, int which) {
    __shared__ __align__(16) float Xq[64][64];
    __shared__ __align__(16) float Xkv[64][64];
    __shared__ __align__(16) float Ws[64][64];
    const float* qsrc  = g_c[which];
    const float* kvsrc = g_c[which ^ 1];
    int bh = blockIdx.y;
    int h = bh & (NH-1);
    int s0 = blockIdx.x * 64;
    int tid = threadIdx.x, tx = tid & 15, ty = tid >> 4;
    int lrow = tid >> 2;
    const float* qbase  = qsrc  + ((size_t)bh*NS + s0)*ND;
    const float* kvbase = kvsrc + ((size_t)bh*NS + s0)*ND;
    #pragma unroll
    for (int it = 0; it < 4; it++) {
        int c = ((tid & 3) + it*4) * 4;
        float4 a  = *(const float4*)(qbase  + lrow*64 + c);
        float4 kv = *(const float4*)(kvbase + lrow*64 + c);
        Xq[c+0][lrow]=a.x;  Xq[c+1][lrow]=a.y;  Xq[c+2][lrow]=a.z;  Xq[c+3][lrow]=a.w;
        Xkv[c+0][lrow]=kv.x;Xkv[c+1][lrow]=kv.y;Xkv[c+2][lrow]=kv.z;Xkv[c+3][lrow]=kv.w;
    }
    for (int p = 0; p < 3; p++) {
        const float* wsrc = in_w + ((size_t)h*192 + p*64)*64;
        #pragma unroll
        for (int it = 0; it < 4; it++) {
            int c = ((tid & 3) + it*4) * 4;
            float4 w = *(const float4*)(wsrc + lrow*64 + c);
            Ws[c+0][lrow]=w.x; Ws[c+1][lrow]=w.y; Ws[c+2][lrow]=w.z; Ws[c+3][lrow]=w.w;
        }
        __syncthreads();
        const float (*X)[64] = (p == 0) ? Xq : Xkv;
        float acc[4][4] = {};
        #pragma unroll 8
        for (int d = 0; d < 64; d++) {
            float4 a4 = *(const float4*)(&X[d][ty*4]);
            float4 w4 = *(const float4*)(&Ws[d][tx*4]);
            float a[4] = {a4.x, a4.y, a4.z, a4.w};
            float w[4] = {w4.x, w4.y, w4.z, w4.w};
            #pragma unroll
            for (int i=0;i<4;i++)
                #pragma unroll
                for (int j=0;j<4;j++) acc[i][j] = fmaf(a[i], w[j], acc[i][j]);
        }
        float* dst = (p==0) ? g_q[which] : (p==1) ? g_k[which] : g_v[which];
        float qscale = (p==0) ? 0.125f : 1.f;
        #pragma unroll
        for (int i=0;i<4;i++){
            int s = s0 + ty*4 + i;
            #pragma unroll
            for (int j=0;j<4;j++){
                int e = tx*4 + j;
                dst[((size_t)bh*NS + s)*ND + e] = (acc[i][j] + in_b[h*192 + p*64 + e]) * qscale;
            }
        }
        __syncthreads();
    }
}

// ---------------- flash attention with mma.sync tf32 tensor cores ----------------
// CTA: 256 threads = 8 warps arranged 4(m) x 2(n). 64-query tile, 64-key KV tiles.
#define PAD 76
__global__ void attn_kernel(int which) {
    extern __shared__ __align__(16) float sm[];
    float* qs = sm;                     // 64*PAD, reused as ps after Q frags built
    float* ks = sm + 64*PAD;
    float* vs = sm + 2*64*PAD;
    float* rowm = sm + 3*64*PAD;
    float* rowl = rowm + 64;
    float* rowf = rowl + 64;
    float* ps = qs;

    const float* Q = g_q[which];
    const float* K = g_k[which];
    const float* V = g_v[which];
    float* O = g_o[which];
    int bh = blockIdx.y, q0 = blockIdx.x * 64;
    int tid = threadIdx.x;
    int wid = tid >> 5, lane = tid & 31;
    int wm = wid >> 1, wn = wid & 1;
    int g = lane >> 2, t = lane & 3;
    int fr0 = wm*16 + g;                // fragment row (and +8)

    // ---- load Q tile (tf32-rounded) into qs ----
    {
        int r = tid >> 2, c0 = (tid & 3) * 16;
        const float* src = Q + ((size_t)bh*NS + q0 + r)*ND + c0;
        float* dst = qs + r*PAD + c0;
        #pragma unroll
        for (int i = 0; i < 4; i++) {
            float4 v4 = *(const float4*)(src + i*4);
            dst[i*4+0]=tf32f(v4.x); dst[i*4+1]=tf32f(v4.y);
            dst[i*4+2]=tf32f(v4.z); dst[i*4+3]=tf32f(v4.w);
        }
    }
    if (tid < 64) { rowm[tid] = -1e30f; rowl[tid] = 0.f; }
    __syncthreads();

    // ---- build persistent Q fragments (8 k-chunks x 4 regs) ----
    unsigned qf[8][4];
    #pragma unroll
    for (int kc = 0; kc < 8; kc++) {
        const float* base = qs + fr0*PAD + kc*8 + t;
        qf[kc][0] = __float_as_uint(base[0]);
        qf[kc][1] = __float_as_uint(base[8*PAD]);
        qf[kc][2] = __float_as_uint(base[4]);
        qf[kc][3] = __float_as_uint(base[8*PAD+4]);
    }
    __syncthreads();   // qs now free -> becomes ps

    float of[4][4] = {};
    for (int j0 = 0; j0 < NS; j0 += 64) {
        // ---- fill K,V tiles (tf32-rounded) ----
        {
            int r = tid >> 2, c0 = (tid & 3) * 16;
            const float* ksrc = K + ((size_t)bh*NS + j0 + r)*ND + c0;
            const float* vsrc = V + ((size_t)bh*NS + j0 + r)*ND + c0;
            float* kd = ks + r*PAD + c0;
            float* vd = vs + r*PAD + c0;
            #pragma unroll
            for (int i = 0; i < 4; i++) {
                float4 kv = *(const float4*)(ksrc + i*4);
                float4 vv = *(const float4*)(vsrc + i*4);
                kd[i*4+0]=tf32f(kv.x); kd[i*4+1]=tf32f(kv.y);
                kd[i*4+2]=tf32f(kv.z); kd[i*4+3]=tf32f(kv.w);
                vd[i*4+0]=tf32f(vv.x); vd[i*4+1]=tf32f(vv.y);
                vd[i*4+2]=tf32f(vv.z); vd[i*4+3]=tf32f(vv.w);
            }
        }
        __syncthreads();

        // ---- S = Q @ K^T via tensor cores ----
        float cf[4][4] = {};
        #pragma unroll
        for (int nt = 0; nt < 4; nt++) {
            int nb = wn*32 + nt*8;
            const float* bbase = ks + (nb + g)*PAD;
            #pragma unroll
            for (int kc = 0; kc < 8; kc++) {
                unsigned b0 = __float_as_uint(bbase[kc*8 + t]);
                unsigned b1 = __float_as_uint(bbase[kc*8 + t + 4]);
                mma_tf32(cf[nt], qf[kc], b0, b1);
            }
        }
        // scatter scores to ps
        #pragma unroll
        for (int nt = 0; nt < 4; nt++) {
            float* p0 = ps + fr0*PAD + wn*32 + nt*8 + 2*t;
            *(float2*)p0 = make_float2(cf[nt][0], cf[nt][1]);
            *(float2*)(p0 + 8*PAD) = make_float2(cf[nt][2], cf[nt][3]);
        }
        __syncthreads();

        // ---- online softmax: 4 threads per row ----
        {
            int r = tid >> 2, c0 = (tid & 3) * 16;
            float* prow = ps + r*PAD;
            float mx = -1e30f;
            #pragma unroll
            for (int i = 0; i < 16; i++) mx = fmaxf(mx, prow[c0+i]);
            mx = fmaxf(mx, __shfl_xor_sync(0xffffffffu, mx, 1));
            mx = fmaxf(mx, __shfl_xor_sync(0xffffffffu, mx, 2));
            float mold = rowm[r];
            float mnew = fmaxf(mold, mx);
            float fr = __expf(mold - mnew);
            float l = 0.f;
            #pragma unroll
            for (int i = 0; i < 16; i++) {
                float e = __expf(prow[c0+i] - mnew);
                prow[c0+i] = tf32f(e);
                l += e;
            }
            l += __shfl_xor_sync(0xffffffffu, l, 1);
            l += __shfl_xor_sync(0xffffffffu, l, 2);
            if ((tid & 3) == 0) {
                rowl[r] = rowl[r]*fr + l;
                rowm[r] = mnew;
                rowf[r] = fr;
            }
        }
        __syncthreads();

        // ---- rescale accumulators ----
        float f0 = rowf[fr0], f1 = rowf[fr0 + 8];
        #pragma unroll
        for (int nt = 0; nt < 4; nt++) {
            of[nt][0] *= f0; of[nt][1] *= f0;
            of[nt][2] *= f1; of[nt][3] *= f1;
        }

        // ---- O += P @ V via tensor cores ----
        #pragma unroll
        for (int kc = 0; kc < 8; kc++) {
            const float* pa = ps + fr0*PAD + kc*8 + t;
            unsigned a[4];
            a[0] = __float_as_uint(pa[0]);
            a[1] = __float_as_uint(pa[8*PAD]);
            a[2] = __float_as_uint(pa[4]);
            a[3] = __float_as_uint(pa[8*PAD+4]);
            #pragma unroll
            for (int nt = 0; nt < 4; nt++) {
                int nb = wn*32 + nt*8;
                unsigned b0 = __float_as_uint(vs[(kc*8 + t)*PAD + nb + g]);
                unsigned b1 = __float_as_uint(vs[(kc*8 + t + 4)*PAD + nb + g]);
                mma_tf32(of[nt], a, b0, b1);
            }
        }
        __syncthreads();
    }

    // ---- epilogue: normalize and store ----
    float il0 = 1.f / rowl[fr0];
    float il1 = 1.f / rowl[fr0 + 8];
    #pragma unroll
    for (int nt = 0; nt < 4; nt++) {
        int col = wn*32 + nt*8 + 2*t;
        float* o0 = O + ((size_t)bh*NS + q0 + fr0)*ND + col;
        float* o1 = O + ((size_t)bh*NS + q0 + fr0 + 8)*ND + col;
        *(float2*)o0 = make_float2(of[nt][0]*il0, of[nt][1]*il0);
        *(float2*)o1 = make_float2(of[nt][2]*il1, of[nt][3]*il1);
    }
}

// ---------------- out projection + residual ----------------
__global__ void outproj_kernel(const float* __restrict__ out_w, const float* __restrict__ out_b, int which) {
    __shared__ __align__(16) float Xs[64][64];
    __shared__ __align__(16) float Ws[64][64];
    const float* Oin   = g_o[which];
    const float* resid = g_c[which];
    int bh = blockIdx.y, h = bh & (NH-1), s0 = blockIdx.x*64;
    int tid = threadIdx.x, tx = tid&15, ty = tid>>4, lrow = tid>>2;
    const float* xbase = Oin + ((size_t)bh*NS + s0)*ND;
    const float* wsrc  = out_w + (size_t)h*64*64;
    #pragma unroll
    for (int it=0; it<4; it++){
        int c = ((tid&3)+it*4)*4;
        float4 x = *(const float4*)(xbase + lrow*64 + c);
        float4 w = *(const float4*)(wsrc  + lrow*64 + c);
        Xs[c+0][lrow]=x.x; Xs[c+1][lrow]=x.y; Xs[c+2][lrow]=x.z; Xs[c+3][lrow]=x.w;
        Ws[c+0][lrow]=w.x; Ws[c+1][lrow]=w.y; Ws[c+2][lrow]=w.z; Ws[c+3][lrow]=w.w;
    }
    __syncthreads();
    float acc[4][4] = {};
    #pragma unroll 8
    for (int e = 0; e < 64; e++) {
        float4 a4 = *(const float4*)(&Xs[e][ty*4]);
        float4 w4 = *(const float4*)(&Ws[e][tx*4]);
        float a[4] = {a4.x, a4.y, a4.z, a4.w};
        float w[4] = {w4.x, w4.y, w4.z, w4.w};
        #pragma unroll
        for (int i=0;i<4;i++)
            #pragma unroll
            for (int j=0;j<4;j++) acc[i][j] = fmaf(a[i], w[j], acc[i][j]);
    }
    int off = which * 64;
    #pragma unroll
    for (int i=0;i<4;i++){
        int s = s0 + ty*4 + i;
        #pragma unroll
        for (int j=0;j<4;j++){
            int f = tx*4 + j;
            g_comb[((size_t)bh*NS + s)*128 + off + f] =
                acc[i][j] + out_b[h*64+f] + resid[((size_t)bh*NS+s)*ND + f];
        }
    }
}

// ---------------- final LN over concat dim (128) ----------------
__global__ void final_ln_kernel(const float* __restrict__ hg, const float* __restrict__ hb,
                                float* __restrict__ out) {
    int row = blockIdx.x * 8 + (threadIdx.x >> 5);
    int lane = threadIdx.x & 31;
    const float* x = g_comb + (size_t)row * 128;
    float v[4], sum = 0.f;
    #pragma unroll
    for (int i=0;i<4;i++){ v[i] = x[lane + i*32]; sum += v[i]; }
    #pragma unroll
    for (int o = 16; o > 0; o >>= 1) sum += __shfl_xor_sync(0xffffffffu, sum, o);
    float mu = sum * (1.f/128.f);
    float sq = 0.f;
    #pragma unroll
    for (int i=0;i<4;i++){ float d = v[i]-mu; sq += d*d; }
    #pragma unroll
    for (int o = 16; o > 0; o >>= 1) sq += __shfl_xor_sync(0xffffffffu, sq, o);
    float rstd = rsqrtf(sq*(1.f/128.f) + 1e-5f);
    int h = (row >> 9) & 15;
    #pragma unroll
    for (int i=0;i<4;i++){
        int c = lane + i*32;
        out[(size_t)row*128 + c] = (v[i]-mu)*rstd*hg[h*128+c] + hb[h*128+c];
    }
}

// ---------------- launch ----------------
extern "C" void kernel_launch(void* const* d_in, const int* in_sizes, int n_in,
                              void* d_out, int out_size) {
    const float* image     = (const float*)d_in[0];
    const float* text      = (const float*)d_in[1];
    const float* img_w     = (const float*)d_in[2];
    const float* img_b     = (const float*)d_in[3];
    const float* img_g     = (const float*)d_in[4];
    const float* img_lb    = (const float*)d_in[5];
    const float* txt_w     = (const float*)d_in[6];
    const float* txt_b     = (const float*)d_in[7];
    const float* txt_g     = (const float*)d_in[8];
    const float* txt_lb    = (const float*)d_in[9];
    const float* i2t_in_w  = (const float*)d_in[10];
    const float* i2t_in_b  = (const float*)d_in[11];
    const float* i2t_out_w = (const float*)d_in[12];
    const float* i2t_out_b = (const float*)d_in[13];
    const float* t2i_in_w  = (const float*)d_in[14];
    const float* t2i_in_b  = (const float*)d_in[15];
    const float* t2i_out_w = (const float*)d_in[16];
    const float* t2i_out_b = (const float*)d_in[17];
    const float* hn_g      = (const float*)d_in[18];
    const float* hn_b      = (const float*)d_in[19];
    float* out = (float*)d_out;

    const int ATTN_SMEM = (3*64*PAD + 3*64) * 4;   // 59136 B
    static int attn_smem_set = 0;
    if (!attn_smem_set) {
        cudaFuncSetAttribute(attn_kernel, cudaFuncAttributeMaxDynamicSharedMemorySize, ATTN_SMEM);
        attn_smem_set = 1;
    }

    dim3 thr(256);
    gemm_bias_kernel<<<dim3(16,128), thr>>>(image, img_w, img_b, 768, 0);
    gemm_bias_kernel<<<dim3(16,128), thr>>>(text,  txt_w, txt_b, 512, 1);
    ln_l2_kernel<<<8192, thr>>>(img_g, img_lb, 0);
    ln_l2_kernel<<<8192, thr>>>(txt_g, txt_lb, 1);
    qkv_kernel<<<dim3(8,256), thr>>>(i2t_in_w, i2t_in_b, 0);
    qkv_kernel<<<dim3(8,256), thr>>>(t2i_in_w, t2i_in_b, 1);
    attn_kernel<<<dim3(8,256), thr, ATTN_SMEM>>>(0);
    attn_kernel<<<dim3(8,256), thr, ATTN_SMEM>>>(1);
    outproj_kernel<<<dim3(8,256), thr>>>(i2t_out_w, i2t_out_b, 0);
    outproj_kernel<<<dim3(8,256), thr>>>(t2i_out_w, t2i_out_b, 1);
    final_ln_kernel<<<16384, thr>>>(hn_g, hn_b, out);
}

// round 4
// speedup vs baseline: 2.6365x; 1.6402x over previous
#include <cuda_runtime.h>
#include <math.h>

#define NB 16
#define NS 512
#define NH 16
#define ND 64
#define NHID 1024
#define NROW (NB*NS)        // 8192
#define NBH (NB*NH)         // 256
#define NTOK (NBH*NS*ND)    // 8388608

// ---------------- scratch (static __device__, allocation-guard safe) ----------------
__device__ __align__(16) float g_proj[2][NROW*NHID];
__device__ __align__(16) float g_c[2][NTOK];           // (B,H,S,D)
__device__ __align__(16) float g_q[2][NTOK];
__device__ __align__(16) float g_k[2][NTOK];
__device__ __align__(16) float g_v[2][NTOK];
__device__ __align__(16) float g_o[2][NTOK];
__device__ __align__(16) float g_comb[NBH*NS*2*ND];    // (B,H,S,128)

// ---------------- tf32 mma helpers ----------------
__device__ __forceinline__ unsigned cvt_tf32(float x) {
    unsigned u; asm("cvt.rna.tf32.f32 %0, %1;" : "=r"(u) : "f"(x)); return u;
}
__device__ __forceinline__ float tf32f(float x) {
    return __uint_as_float(cvt_tf32(x));
}
__device__ __forceinline__ void mma_tf32(float c[4], const unsigned a[4], unsigned b0, unsigned b1) {
    asm("mma.sync.aligned.m16n8k8.row.col.f32.tf32.tf32.f32 "
        "{%0,%1,%2,%3}, {%4,%5,%6,%7}, {%8,%9}, {%0,%1,%2,%3};"
        : "+f"(c[0]), "+f"(c[1]), "+f"(c[2]), "+f"(c[3])
        : "r"(a[0]), "r"(a[1]), "r"(a[2]), "r"(a[3]), "r"(b0), "r"(b1));
}

// ============ big projection GEMM (tf32 tensor cores) ============
// C[M,1024] = A[M,K] @ W[1024,K]^T + bias.  CTA tile 128x128, BK=32.
#define GPA 36    // 32 + 4 pad -> (4g+t) bank-unique fragment gathers
__global__ void gemm_tf32_kernel(const float* __restrict__ A,
                                 const float* __restrict__ W,
                                 const float* __restrict__ bias,
                                 int K, int which) {
    __shared__ __align__(16) float As[128*GPA];
    __shared__ __align__(16) float Ws[128*GPA];
    float* C = g_proj[which];
    int tid = threadIdx.x;
    int wid = tid >> 5, lane = tid & 31;
    int wm = wid >> 1, wn = wid & 1;
    int g = lane >> 2, t = lane & 3;
    int m0 = blockIdx.y * 128, n0 = blockIdx.x * 128;
    int lr = tid >> 3;           // 0..31
    int lc = (tid & 7) * 4;      // 0..28
    float acc[2][8][4] = {};
    for (int k0 = 0; k0 < K; k0 += 32) {
        #pragma unroll
        for (int i = 0; i < 4; i++) {
            int r = lr + i*32;
            float4 av = *(const float4*)(A + (size_t)(m0 + r)*K + k0 + lc);
            float4 wv = *(const float4*)(W + (size_t)(n0 + r)*K + k0 + lc);
            float* ad = As + r*GPA + lc;
            float* wd = Ws + r*GPA + lc;
            ad[0]=tf32f(av.x); ad[1]=tf32f(av.y); ad[2]=tf32f(av.z); ad[3]=tf32f(av.w);
            wd[0]=tf32f(wv.x); wd[1]=tf32f(wv.y); wd[2]=tf32f(wv.z); wd[3]=tf32f(wv.w);
        }
        __syncthreads();
        #pragma unroll
        for (int kc = 0; kc < 4; kc++) {
            unsigned a[2][4];
            #pragma unroll
            for (int mf = 0; mf < 2; mf++) {
                const float* ab = As + (wm*32 + mf*16 + g)*GPA + kc*8 + t;
                a[mf][0] = __float_as_uint(ab[0]);
                a[mf][1] = __float_as_uint(ab[8*GPA]);
                a[mf][2] = __float_as_uint(ab[4]);
                a[mf][3] = __float_as_uint(ab[8*GPA+4]);
            }
            #pragma unroll
            for (int nf = 0; nf < 8; nf++) {
                const float* bb = Ws + (wn*64 + nf*8 + g)*GPA + kc*8 + t;
                unsigned b0 = __float_as_uint(bb[0]);
                unsigned b1 = __float_as_uint(bb[4]);
                mma_tf32(acc[0][nf], a[0], b0, b1);
                mma_tf32(acc[1][nf], a[1], b0, b1);
            }
        }
        __syncthreads();
    }
    #pragma unroll
    for (int mf = 0; mf < 2; mf++) {
        int r0 = m0 + wm*32 + mf*16 + g;
        #pragma unroll
        for (int nf = 0; nf < 8; nf++) {
            int c = n0 + wn*64 + nf*8 + 2*t;
            float bx = bias[c], by = bias[c+1];
            *(float2*)(C + (size_t)r0*NHID + c) =
                make_float2(acc[mf][nf][0] + bx, acc[mf][nf][1] + by);
            *(float2*)(C + (size_t)(r0+8)*NHID + c) =
                make_float2(acc[mf][nf][2] + bx, acc[mf][nf][3] + by);
        }
    }
}

// ---------------- LN + l2-normalize + D^-0.5, writes (B,H,S,D) layout ----------------
__device__ __forceinline__ float breduce256(float v, float* red) {
    #pragma unroll
    for (int o = 16; o > 0; o >>= 1) v += __shfl_xor_sync(0xffffffffu, v, o);
    int tid = threadIdx.x;
    if ((tid & 31) == 0) red[tid >> 5] = v;
    __syncthreads();
    float t = 0.f;
    #pragma unroll
    for (int i = 0; i < 8; i++) t += red[i];
    __syncthreads();
    return t;
}

__global__ void ln_l2_kernel(const float* __restrict__ g, const float* __restrict__ b, int which) {
    __shared__ float red[8];
    int row = blockIdx.x;
    int tid = threadIdx.x;
    const float* y = g_proj[which] + (size_t)row * NHID;
    float v[4], sum = 0.f;
    #pragma unroll
    for (int i=0;i<4;i++){ v[i] = y[tid + i*256]; sum += v[i]; }
    sum = breduce256(sum, red);
    float mu = sum * (1.f/NHID);
    float sq = 0.f;
    #pragma unroll
    for (int i=0;i<4;i++){ float d = v[i]-mu; sq += d*d; }
    sq = breduce256(sq, red);
    float rstd = rsqrtf(sq*(1.f/NHID) + 1e-5f);
    float ln[4], s2 = 0.f;
    #pragma unroll
    for (int i=0;i<4;i++){ int n = tid+i*256; ln[i] = (v[i]-mu)*rstd*g[n] + b[n]; s2 += ln[i]*ln[i]; }
    s2 = breduce256(s2, red);
    float scale = 0.125f / fmaxf(sqrtf(s2), 1e-12f);
    int bb = row >> 9, s = row & 511;
    float* outp = g_c[which];
    #pragma unroll
    for (int i=0;i<4;i++){
        int n = tid + i*256;
        int h = n >> 6, d = n & 63;
        outp[(((size_t)(bb*NH + h))*NS + s)*ND + d] = ln[i]*scale;
    }
}

// ============ per-head QKV projection (tf32 tensor cores) ============
#define QPA 68    // 64 + 4 pad
__global__ void qkv_tf32_kernel(const float* __restrict__ in_w,
                                const float* __restrict__ in_b, int which) {
    extern __shared__ __align__(16) float sm[];
    float* Xq  = sm;                 // [s][d] 64*68
    float* Xkv = sm + 64*QPA;
    float* Wsm = sm + 2*64*QPA;      // [e][d]
    int bh = blockIdx.y;
    int h = bh & (NH-1);
    int s0 = blockIdx.x * 64;
    int tid = threadIdx.x;
    int wid = tid >> 5, lane = tid & 31;
    int wm = wid >> 1, wn = wid & 1;
    int g = lane >> 2, t = lane & 3;
    int fr0 = wm*16 + g;
    int lr = tid >> 4;             // 0..15
    int lc = (tid & 15) * 4;       // 0..60
    const float* qbase  = g_c[which]   + ((size_t)bh*NS + s0)*ND;
    const float* kvbase = g_c[which^1] + ((size_t)bh*NS + s0)*ND;
    #pragma unroll
    for (int i = 0; i < 4; i++) {
        int r = lr + i*16;
        float4 a  = *(const float4*)(qbase  + r*ND + lc);
        float4 kv = *(const float4*)(kvbase + r*ND + lc);
        float* qd = Xq + r*QPA + lc;
        float* kd = Xkv + r*QPA + lc;
        qd[0]=tf32f(a.x);  qd[1]=tf32f(a.y);  qd[2]=tf32f(a.z);  qd[3]=tf32f(a.w);
        kd[0]=tf32f(kv.x); kd[1]=tf32f(kv.y); kd[2]=tf32f(kv.z); kd[3]=tf32f(kv.w);
    }
    __syncthreads();
    unsigned aq[8][4], akv[8][4];
    #pragma unroll
    for (int kc = 0; kc < 8; kc++) {
        const float* qb = Xq  + fr0*QPA + kc*8 + t;
        const float* kb = Xkv + fr0*QPA + kc*8 + t;
        aq[kc][0]=__float_as_uint(qb[0]);        aq[kc][1]=__float_as_uint(qb[8*QPA]);
        aq[kc][2]=__float_as_uint(qb[4]);        aq[kc][3]=__float_as_uint(qb[8*QPA+4]);
        akv[kc][0]=__float_as_uint(kb[0]);       akv[kc][1]=__float_as_uint(kb[8*QPA]);
        akv[kc][2]=__float_as_uint(kb[4]);       akv[kc][3]=__float_as_uint(kb[8*QPA+4]);
    }
    for (int p = 0; p < 3; p++) {
        if (p) __syncthreads();
        const float* wsrc = in_w + ((size_t)h*192 + p*64)*64;   // [e][d]
        #pragma unroll
        for (int i = 0; i < 4; i++) {
            int r = lr + i*16;
            float4 w = *(const float4*)(wsrc + r*64 + lc);
            float* wd = Wsm + r*QPA + lc;
            wd[0]=tf32f(w.x); wd[1]=tf32f(w.y); wd[2]=tf32f(w.z); wd[3]=tf32f(w.w);
        }
        __syncthreads();
        float acc[4][4] = {};
        #pragma unroll
        for (int kc = 0; kc < 8; kc++) {
            const unsigned* a = (p == 0) ? aq[kc] : akv[kc];
            #pragma unroll
            for (int nt = 0; nt < 4; nt++) {
                const float* bb = Wsm + (wn*32 + nt*8 + g)*QPA + kc*8 + t;
                mma_tf32(acc[nt], a, __float_as_uint(bb[0]), __float_as_uint(bb[4]));
            }
        }
        float* dst = (p==0) ? g_q[which] : (p==1) ? g_k[which] : g_v[which];
        float qscale = (p==0) ? 0.125f : 1.f;
        const float* bsrc = in_b + h*192 + p*64;
        #pragma unroll
        for (int nt = 0; nt < 4; nt++) {
            int c = wn*32 + nt*8 + 2*t;
            float bx = bsrc[c], by = bsrc[c+1];
            float* o0 = dst + ((size_t)bh*NS + s0 + fr0)*ND + c;
            float* o1 = dst + ((size_t)bh*NS + s0 + fr0 + 8)*ND + c;
            *(float2*)o0 = make_float2((acc[nt][0]+bx)*qscale, (acc[nt][1]+by)*qscale);
            *(float2*)o1 = make_float2((acc[nt][2]+bx)*qscale, (acc[nt][3]+by)*qscale);
        }
    }
}

// ---------------- flash attention with mma.sync tf32 tensor cores ----------------
#define PAD 76
__global__ void attn_kernel(int which) {
    extern __shared__ __align__(16) float sm[];
    float* qs = sm;
    float* ks = sm + 64*PAD;
    float* vs = sm + 2*64*PAD;
    float* rowm = sm + 3*64*PAD;
    float* rowl = rowm + 64;
    float* rowf = rowl + 64;
    float* ps = qs;

    const float* Q = g_q[which];
    const float* K = g_k[which];
    const float* V = g_v[which];
    float* O = g_o[which];
    int bh = blockIdx.y, q0 = blockIdx.x * 64;
    int tid = threadIdx.x;
    int wid = tid >> 5, lane = tid & 31;
    int wm = wid >> 1, wn = wid & 1;
    int g = lane >> 2, t = lane & 3;
    int fr0 = wm*16 + g;

    {
        int r = tid >> 2, c0 = (tid & 3) * 16;
        const float* src = Q + ((size_t)bh*NS + q0 + r)*ND + c0;
        float* dst = qs + r*PAD + c0;
        #pragma unroll
        for (int i = 0; i < 4; i++) {
            float4 v4 = *(const float4*)(src + i*4);
            dst[i*4+0]=tf32f(v4.x); dst[i*4+1]=tf32f(v4.y);
            dst[i*4+2]=tf32f(v4.z); dst[i*4+3]=tf32f(v4.w);
        }
    }
    if (tid < 64) { rowm[tid] = -1e30f; rowl[tid] = 0.f; }
    __syncthreads();

    unsigned qf[8][4];
    #pragma unroll
    for (int kc = 0; kc < 8; kc++) {
        const float* base = qs + fr0*PAD + kc*8 + t;
        qf[kc][0] = __float_as_uint(base[0]);
        qf[kc][1] = __float_as_uint(base[8*PAD]);
        qf[kc][2] = __float_as_uint(base[4]);
        qf[kc][3] = __float_as_uint(base[8*PAD+4]);
    }
    __syncthreads();

    float of[4][4] = {};
    for (int j0 = 0; j0 < NS; j0 += 64) {
        {
            int r = tid >> 2, c0 = (tid & 3) * 16;
            const float* ksrc = K + ((size_t)bh*NS + j0 + r)*ND + c0;
            const float* vsrc = V + ((size_t)bh*NS + j0 + r)*ND + c0;
            float* kd = ks + r*PAD + c0;
            float* vd = vs + r*PAD + c0;
            #pragma unroll
            for (int i = 0; i < 4; i++) {
                float4 kv = *(const float4*)(ksrc + i*4);
                float4 vv = *(const float4*)(vsrc + i*4);
                kd[i*4+0]=tf32f(kv.x); kd[i*4+1]=tf32f(kv.y);
                kd[i*4+2]=tf32f(kv.z); kd[i*4+3]=tf32f(kv.w);
                vd[i*4+0]=tf32f(vv.x); vd[i*4+1]=tf32f(vv.y);
                vd[i*4+2]=tf32f(vv.z); vd[i*4+3]=tf32f(vv.w);
            }
        }
        __syncthreads();

        float cf[4][4] = {};
        #pragma unroll
        for (int nt = 0; nt < 4; nt++) {
            int nb = wn*32 + nt*8;
            const float* bbase = ks + (nb + g)*PAD;
            #pragma unroll
            for (int kc = 0; kc < 8; kc++) {
                unsigned b0 = __float_as_uint(bbase[kc*8 + t]);
                unsigned b1 = __float_as_uint(bbase[kc*8 + t + 4]);
                mma_tf32(cf[nt], qf[kc], b0, b1);
            }
        }
        #pragma unroll
        for (int nt = 0; nt < 4; nt++) {
            float* p0 = ps + fr0*PAD + wn*32 + nt*8 + 2*t;
            *(float2*)p0 = make_float2(cf[nt][0], cf[nt][1]);
            *(float2*)(p0 + 8*PAD) = make_float2(cf[nt][2], cf[nt][3]);
        }
        __syncthreads();

        {
            int r = tid >> 2, c0 = (tid & 3) * 16;
            float* prow = ps + r*PAD;
            float mx = -1e30f;
            #pragma unroll
            for (int i = 0; i < 16; i++) mx = fmaxf(mx, prow[c0+i]);
            mx = fmaxf(mx, __shfl_xor_sync(0xffffffffu, mx, 1));
            mx = fmaxf(mx, __shfl_xor_sync(0xffffffffu, mx, 2));
            float mold = rowm[r];
            float mnew = fmaxf(mold, mx);
            float fr = __expf(mold - mnew);
            float l = 0.f;
            #pragma unroll
            for (int i = 0; i < 16; i++) {
                float e = __expf(prow[c0+i] - mnew);
                prow[c0+i] = tf32f(e);
                l += e;
            }
            l += __shfl_xor_sync(0xffffffffu, l, 1);
            l += __shfl_xor_sync(0xffffffffu, l, 2);
            if ((tid & 3) == 0) {
                rowl[r] = rowl[r]*fr + l;
                rowm[r] = mnew;
                rowf[r] = fr;
            }
        }
        __syncthreads();

        float f0 = rowf[fr0], f1 = rowf[fr0 + 8];
        #pragma unroll
        for (int nt = 0; nt < 4; nt++) {
            of[nt][0] *= f0; of[nt][1] *= f0;
            of[nt][2] *= f1; of[nt][3] *= f1;
        }

        #pragma unroll
        for (int kc = 0; kc < 8; kc++) {
            const float* pa = ps + fr0*PAD + kc*8 + t;
            unsigned a[4];
            a[0] = __float_as_uint(pa[0]);
            a[1] = __float_as_uint(pa[8*PAD]);
            a[2] = __float_as_uint(pa[4]);
            a[3] = __float_as_uint(pa[8*PAD+4]);
            #pragma unroll
            for (int nt = 0; nt < 4; nt++) {
                int nb = wn*32 + nt*8;
                unsigned b0 = __float_as_uint(vs[(kc*8 + t)*PAD + nb + g]);
                unsigned b1 = __float_as_uint(vs[(kc*8 + t + 4)*PAD + nb + g]);
                mma_tf32(of[nt], a, b0, b1);
            }
        }
        __syncthreads();
    }

    float il0 = 1.f / rowl[fr0];
    float il1 = 1.f / rowl[fr0 + 8];
    #pragma unroll
    for (int nt = 0; nt < 4; nt++) {
        int col = wn*32 + nt*8 + 2*t;
        float* o0 = O + ((size_t)bh*NS + q0 + fr0)*ND + col;
        float* o1 = O + ((size_t)bh*NS + q0 + fr0 + 8)*ND + col;
        *(float2*)o0 = make_float2(of[nt][0]*il0, of[nt][1]*il0);
        *(float2*)o1 = make_float2(of[nt][2]*il1, of[nt][3]*il1);
    }
}

// ============ out projection + residual (tf32 tensor cores) ============
__global__ void outproj_tf32_kernel(const float* __restrict__ out_w,
                                    const float* __restrict__ out_b, int which) {
    __shared__ __align__(16) float Xs[64*QPA];
    __shared__ __align__(16) float Wsm[64*QPA];
    int bh = blockIdx.y, h = bh & (NH-1), s0 = blockIdx.x*64;
    int tid = threadIdx.x;
    int wid = tid >> 5, lane = tid & 31;
    int wm = wid >> 1, wn = wid & 1;
    int g = lane >> 2, t = lane & 3;
    int fr0 = wm*16 + g;
    int lr = tid >> 4, lc = (tid & 15) * 4;
    const float* xbase = g_o[which] + ((size_t)bh*NS + s0)*ND;
    const float* wsrc  = out_w + (size_t)h*64*64;   // [f][e]
    #pragma unroll
    for (int i = 0; i < 4; i++) {
        int r = lr + i*16;
        float4 x = *(const float4*)(xbase + r*ND + lc);
        float4 w = *(const float4*)(wsrc  + r*64 + lc);
        float* xd = Xs + r*QPA + lc;
        float* wd = Wsm + r*QPA + lc;
        xd[0]=tf32f(x.x); xd[1]=tf32f(x.y); xd[2]=tf32f(x.z); xd[3]=tf32f(x.w);
        wd[0]=tf32f(w.x); wd[1]=tf32f(w.y); wd[2]=tf32f(w.z); wd[3]=tf32f(w.w);
    }
    __syncthreads();
    float acc[4][4] = {};
    #pragma unroll
    for (int kc = 0; kc < 8; kc++) {
        const float* ab = Xs + fr0*QPA + kc*8 + t;
        unsigned a[4];
        a[0]=__float_as_uint(ab[0]);  a[1]=__float_as_uint(ab[8*QPA]);
        a[2]=__float_as_uint(ab[4]);  a[3]=__float_as_uint(ab[8*QPA+4]);
        #pragma unroll
        for (int nt = 0; nt < 4; nt++) {
            const float* bb = Wsm + (wn*32 + nt*8 + g)*QPA + kc*8 + t;
            mma_tf32(acc[nt], a, __float_as_uint(bb[0]), __float_as_uint(bb[4]));
        }
    }
    const float* resid = g_c[which];
    int off = which * 64;
    #pragma unroll
    for (int nt = 0; nt < 4; nt++) {
        int c = wn*32 + nt*8 + 2*t;
        float bx = out_b[h*64+c], by = out_b[h*64+c+1];
        int s0r = s0 + fr0, s1r = s0 + fr0 + 8;
        const float* r0 = resid + ((size_t)bh*NS + s0r)*ND + c;
        const float* r1 = resid + ((size_t)bh*NS + s1r)*ND + c;
        float* d0 = g_comb + ((size_t)bh*NS + s0r)*128 + off + c;
        float* d1 = g_comb + ((size_t)bh*NS + s1r)*128 + off + c;
        *(float2*)d0 = make_float2(acc[nt][0]+bx+r0[0], acc[nt][1]+by+r0[1]);
        *(float2*)d1 = make_float2(acc[nt][2]+bx+r1[0], acc[nt][3]+by+r1[1]);
    }
}

// ---------------- final LN over concat dim (128) ----------------
__global__ void final_ln_kernel(const float* __restrict__ hg, const float* __restrict__ hb,
                                float* __restrict__ out) {
    int row = blockIdx.x * 8 + (threadIdx.x >> 5);
    int lane = threadIdx.x & 31;
    const float* x = g_comb + (size_t)row * 128;
    float v[4], sum = 0.f;
    #pragma unroll
    for (int i=0;i<4;i++){ v[i] = x[lane + i*32]; sum += v[i]; }
    #pragma unroll
    for (int o = 16; o > 0; o >>= 1) sum += __shfl_xor_sync(0xffffffffu, sum, o);
    float mu = sum * (1.f/128.f);
    float sq = 0.f;
    #pragma unroll
    for (int i=0;i<4;i++){ float d = v[i]-mu; sq += d*d; }
    #pragma unroll
    for (int o = 16; o > 0; o >>= 1) sq += __shfl_xor_sync(0xffffffffu, sq, o);
    float rstd = rsqrtf(sq*(1.f/128.f) + 1e-5f);
    int h = (row >> 9) & 15;
    #pragma unroll
    for (int i=0;i<4;i++){
        int c = lane + i*32;
        out[(size_t)row*128 + c] = (v[i]-mu)*rstd*hg[h*128+c] + hb[h*128+c];
    }
}

// ---------------- launch ----------------
extern "C" void kernel_launch(void* const* d_in, const int* in_sizes, int n_in,
                              void* d_out, int out_size) {
    const float* image     = (const float*)d_in[0];
    const float* text      = (const float*)d_in[1];
    const float* img_w     = (const float*)d_in[2];
    const float* img_b     = (const float*)d_in[3];
    const float* img_g     = (const float*)d_in[4];
    const float* img_lb    = (const float*)d_in[5];
    const float* txt_w     = (const float*)d_in[6];
    const float* txt_b     = (const float*)d_in[7];
    const float* txt_g     = (const float*)d_in[8];
    const float* txt_lb    = (const float*)d_in[9];
    const float* i2t_in_w  = (const float*)d_in[10];
    const float* i2t_in_b  = (const float*)d_in[11];
    const float* i2t_out_w = (const float*)d_in[12];
    const float* i2t_out_b = (const float*)d_in[13];
    const float* t2i_in_w  = (const float*)d_in[14];
    const float* t2i_in_b  = (const float*)d_in[15];
    const float* t2i_out_w = (const float*)d_in[16];
    const float* t2i_out_b = (const float*)d_in[17];
    const float* hn_g      = (const float*)d_in[18];
    const float* hn_b      = (const float*)d_in[19];
    float* out = (float*)d_out;

    const int ATTN_SMEM = (3*64*PAD + 3*64) * 4;     // 59136 B
    const int QKV_SMEM  = 3*64*QPA*4;                // 52224 B
    static int attrs_set = 0;
    if (!attrs_set) {
        cudaFuncSetAttribute(attn_kernel, cudaFuncAttributeMaxDynamicSharedMemorySize, ATTN_SMEM);
        cudaFuncSetAttribute(qkv_tf32_kernel, cudaFuncAttributeMaxDynamicSharedMemorySize, QKV_SMEM);
        attrs_set = 1;
    }

    dim3 thr(256);
    gemm_tf32_kernel<<<dim3(8,64), thr>>>(image, img_w, img_b, 768, 0);
    gemm_tf32_kernel<<<dim3(8,64), thr>>>(text,  txt_w, txt_b, 512, 1);
    ln_l2_kernel<<<8192, thr>>>(img_g, img_lb, 0);
    ln_l2_kernel<<<8192, thr>>>(txt_g, txt_lb, 1);
    qkv_tf32_kernel<<<dim3(8,256), thr, QKV_SMEM>>>(i2t_in_w, i2t_in_b, 0);
    qkv_tf32_kernel<<<dim3(8,256), thr, QKV_SMEM>>>(t2i_in_w, t2i_in_b, 1);
    attn_kernel<<<dim3(8,256), thr, ATTN_SMEM>>>(0);
    attn_kernel<<<dim3(8,256), thr, ATTN_SMEM>>>(1);
    outproj_tf32_kernel<<<dim3(8,256), thr>>>(i2t_out_w, i2t_out_b, 0);
    outproj_tf32_kernel<<<dim3(8,256), thr>>>(t2i_out_w, t2i_out_b, 1);
    final_ln_kernel<<<16384, thr>>>(hn_g, hn_b, out);
}

// round 5
// speedup vs baseline: 2.6377x; 1.0005x over previous
#include <cuda_runtime.h>
#include <math.h>

#define NB 16
#define NS 512
#define NH 16
#define ND 64
#define NHID 1024
#define NROW (NB*NS)        // 8192
#define NBH (NB*NH)         // 256
#define NTOK (NBH*NS*ND)    // 8388608

// ---------------- scratch (static __device__, allocation-guard safe) ----------------
__device__ __align__(16) float g_proj[2][NROW*NHID];
__device__ __align__(16) float g_c[2][NTOK];           // (B,H,S,D)
__device__ __align__(16) float g_q[2][NTOK];
__device__ __align__(16) float g_k[2][NTOK];
__device__ __align__(16) float g_v[2][NTOK];
__device__ __align__(16) float g_o[2][NTOK];
__device__ __align__(16) float g_comb[NBH*NS*2*ND];    // (B,H,S,128)

// ---------------- tf32 mma helpers ----------------
__device__ __forceinline__ unsigned cvt_tf32(float x) {
    unsigned u; asm("cvt.rna.tf32.f32 %0, %1;" : "=r"(u) : "f"(x)); return u;
}
__device__ __forceinline__ float tf32f(float x) {
    return __uint_as_float(cvt_tf32(x));
}
__device__ __forceinline__ void mma_tf32(float c[4], const unsigned a[4], unsigned b0, unsigned b1) {
    asm("mma.sync.aligned.m16n8k8.row.col.f32.tf32.tf32.f32 "
        "{%0,%1,%2,%3}, {%4,%5,%6,%7}, {%8,%9}, {%0,%1,%2,%3};"
        : "+f"(c[0]), "+f"(c[1]), "+f"(c[2]), "+f"(c[3])
        : "r"(a[0]), "r"(a[1]), "r"(a[2]), "r"(a[3]), "r"(b0), "r"(b1));
}

// ============ big projection GEMM (tf32 tensor cores) ============
// C[M,1024] = A[M,K] @ W[1024,K]^T + bias.  CTA tile 128x128, BK=32.
#define GPA 36    // 32 + 4 pad -> (4g+t) bank-unique fragment gathers
__global__ void gemm_tf32_kernel(const float* __restrict__ A,
                                 const float* __restrict__ W,
                                 const float* __restrict__ bias,
                                 int K, int which) {
    __shared__ __align__(16) float As[128*GPA];
    __shared__ __align__(16) float Ws[128*GPA];
    float* C = g_proj[which];
    int tid = threadIdx.x;
    int wid = tid >> 5, lane = tid & 31;
    int wm = wid >> 1, wn = wid & 1;
    int g = lane >> 2, t = lane & 3;
    int m0 = blockIdx.y * 128, n0 = blockIdx.x * 128;
    int lr = tid >> 3;           // 0..31
    int lc = (tid & 7) * 4;      // 0..28
    float acc[2][8][4] = {};
    for (int k0 = 0; k0 < K; k0 += 32) {
        #pragma unroll
        for (int i = 0; i < 4; i++) {
            int r = lr + i*32;
            float4 av = *(const float4*)(A + (size_t)(m0 + r)*K + k0 + lc);
            float4 wv = *(const float4*)(W + (size_t)(n0 + r)*K + k0 + lc);
            float* ad = As + r*GPA + lc;
            float* wd = Ws + r*GPA + lc;
            ad[0]=tf32f(av.x); ad[1]=tf32f(av.y); ad[2]=tf32f(av.z); ad[3]=tf32f(av.w);
            wd[0]=tf32f(wv.x); wd[1]=tf32f(wv.y); wd[2]=tf32f(wv.z); wd[3]=tf32f(wv.w);
        }
        __syncthreads();
        #pragma unroll
        for (int kc = 0; kc < 4; kc++) {
            unsigned a[2][4];
            #pragma unroll
            for (int mf = 0; mf < 2; mf++) {
                const float* ab = As + (wm*32 + mf*16 + g)*GPA + kc*8 + t;
                a[mf][0] = __float_as_uint(ab[0]);
                a[mf][1] = __float_as_uint(ab[8*GPA]);
                a[mf][2] = __float_as_uint(ab[4]);
                a[mf][3] = __float_as_uint(ab[8*GPA+4]);
            }
            #pragma unroll
            for (int nf = 0; nf < 8; nf++) {
                const float* bb = Ws + (wn*64 + nf*8 + g)*GPA + kc*8 + t;
                unsigned b0 = __float_as_uint(bb[0]);
                unsigned b1 = __float_as_uint(bb[4]);
                mma_tf32(acc[0][nf], a[0], b0, b1);
                mma_tf32(acc[1][nf], a[1], b0, b1);
            }
        }
        __syncthreads();
    }
    #pragma unroll
    for (int mf = 0; mf < 2; mf++) {
        int r0 = m0 + wm*32 + mf*16 + g;
        #pragma unroll
        for (int nf = 0; nf < 8; nf++) {
            int c = n0 + wn*64 + nf*8 + 2*t;
            float bx = bias[c], by = bias[c+1];
            *(float2*)(C + (size_t)r0*NHID + c) =
                make_float2(acc[mf][nf][0] + bx, acc[mf][nf][1] + by);
            *(float2*)(C + (size_t)(r0+8)*NHID + c) =
                make_float2(acc[mf][nf][2] + bx, acc[mf][nf][3] + by);
        }
    }
}

// ---------------- LN + l2-normalize + D^-0.5, writes (B,H,S,D) layout ----------------
__device__ __forceinline__ float breduce256(float v, float* red) {
    #pragma unroll
    for (int o = 16; o > 0; o >>= 1) v += __shfl_xor_sync(0xffffffffu, v, o);
    int tid = threadIdx.x;
    if ((tid & 31) == 0) red[tid >> 5] = v;
    __syncthreads();
    float t = 0.f;
    #pragma unroll
    for (int i = 0; i < 8; i++) t += red[i];
    __syncthreads();
    return t;
}

__global__ void ln_l2_kernel(const float* __restrict__ g, const float* __restrict__ b, int which) {
    __shared__ float red[8];
    int row = blockIdx.x;
    int tid = threadIdx.x;
    const float* y = g_proj[which] + (size_t)row * NHID;
    float v[4], sum = 0.f;
    #pragma unroll
    for (int i=0;i<4;i++){ v[i] = y[tid + i*256]; sum += v[i]; }
    sum = breduce256(sum, red);
    float mu = sum * (1.f/NHID);
    float sq = 0.f;
    #pragma unroll
    for (int i=0;i<4;i++){ float d = v[i]-mu; sq += d*d; }
    sq = breduce256(sq, red);
    float rstd = rsqrtf(sq*(1.f/NHID) + 1e-5f);
    float ln[4], s2 = 0.f;
    #pragma unroll
    for (int i=0;i<4;i++){ int n = tid+i*256; ln[i] = (v[i]-mu)*rstd*g[n] + b[n]; s2 += ln[i]*ln[i]; }
    s2 = breduce256(s2, red);
    float scale = 0.125f / fmaxf(sqrtf(s2), 1e-12f);
    int bb = row >> 9, s = row & 511;
    float* outp = g_c[which];
    #pragma unroll
    for (int i=0;i<4;i++){
        int n = tid + i*256;
        int h = n >> 6, d = n & 63;
        outp[(((size_t)(bb*NH + h))*NS + s)*ND + d] = ln[i]*scale;
    }
}

// ============ per-head QKV projection (tf32 tensor cores) ============
#define QPA 68    // 64 + 4 pad
__global__ void qkv_tf32_kernel(const float* __restrict__ in_w,
                                const float* __restrict__ in_b, int which) {
    extern __shared__ __align__(16) float sm[];
    float* Xq  = sm;                 // [s][d] 64*68
    float* Xkv = sm + 64*QPA;
    float* Wsm = sm + 2*64*QPA;      // [e][d]
    int bh = blockIdx.y;
    int h = bh & (NH-1);
    int s0 = blockIdx.x * 64;
    int tid = threadIdx.x;
    int wid = tid >> 5, lane = tid & 31;
    int wm = wid >> 1, wn = wid & 1;
    int g = lane >> 2, t = lane & 3;
    int fr0 = wm*16 + g;
    int lr = tid >> 4;             // 0..15
    int lc = (tid & 15) * 4;       // 0..60
    const float* qbase  = g_c[which]   + ((size_t)bh*NS + s0)*ND;
    const float* kvbase = g_c[which^1] + ((size_t)bh*NS + s0)*ND;
    #pragma unroll
    for (int i = 0; i < 4; i++) {
        int r = lr + i*16;
        float4 a  = *(const float4*)(qbase  + r*ND + lc);
        float4 kv = *(const float4*)(kvbase + r*ND + lc);
        float* qd = Xq + r*QPA + lc;
        float* kd = Xkv + r*QPA + lc;
        qd[0]=tf32f(a.x);  qd[1]=tf32f(a.y);  qd[2]=tf32f(a.z);  qd[3]=tf32f(a.w);
        kd[0]=tf32f(kv.x); kd[1]=tf32f(kv.y); kd[2]=tf32f(kv.z); kd[3]=tf32f(kv.w);
    }
    __syncthreads();
    unsigned aq[8][4], akv[8][4];
    #pragma unroll
    for (int kc = 0; kc < 8; kc++) {
        const float* qb = Xq  + fr0*QPA + kc*8 + t;
        const float* kb = Xkv + fr0*QPA + kc*8 + t;
        aq[kc][0]=__float_as_uint(qb[0]);        aq[kc][1]=__float_as_uint(qb[8*QPA]);
        aq[kc][2]=__float_as_uint(qb[4]);        aq[kc][3]=__float_as_uint(qb[8*QPA+4]);
        akv[kc][0]=__float_as_uint(kb[0]);       akv[kc][1]=__float_as_uint(kb[8*QPA]);
        akv[kc][2]=__float_as_uint(kb[4]);       akv[kc][3]=__float_as_uint(kb[8*QPA+4]);
    }
    for (int p = 0; p < 3; p++) {
        if (p) __syncthreads();
        const float* wsrc = in_w + ((size_t)h*192 + p*64)*64;   // [e][d]
        #pragma unroll
        for (int i = 0; i < 4; i++) {
            int r = lr + i*16;
            float4 w = *(const float4*)(wsrc + r*64 + lc);
            float* wd = Wsm + r*QPA + lc;
            wd[0]=tf32f(w.x); wd[1]=tf32f(w.y); wd[2]=tf32f(w.z); wd[3]=tf32f(w.w);
        }
        __syncthreads();
        float acc[4][4] = {};
        #pragma unroll
        for (int kc = 0; kc < 8; kc++) {
            const unsigned* a = (p == 0) ? aq[kc] : akv[kc];
            #pragma unroll
            for (int nt = 0; nt < 4; nt++) {
                const float* bb = Wsm + (wn*32 + nt*8 + g)*QPA + kc*8 + t;
                mma_tf32(acc[nt], a, __float_as_uint(bb[0]), __float_as_uint(bb[4]));
            }
        }
        float* dst = (p==0) ? g_q[which] : (p==1) ? g_k[which] : g_v[which];
        float qscale = (p==0) ? 0.125f : 1.f;
        const float* bsrc = in_b + h*192 + p*64;
        #pragma unroll
        for (int nt = 0; nt < 4; nt++) {
            int c = wn*32 + nt*8 + 2*t;
            float bx = bsrc[c], by = bsrc[c+1];
            float* o0 = dst + ((size_t)bh*NS + s0 + fr0)*ND + c;
            float* o1 = dst + ((size_t)bh*NS + s0 + fr0 + 8)*ND + c;
            *(float2*)o0 = make_float2((acc[nt][0]+bx)*qscale, (acc[nt][1]+by)*qscale);
            *(float2*)o1 = make_float2((acc[nt][2]+bx)*qscale, (acc[nt][3]+by)*qscale);
        }
    }
}

// ---------------- flash attention with mma.sync tf32 tensor cores ----------------
#define PAD 76
__global__ void attn_kernel(int which) {
    extern __shared__ __align__(16) float sm[];
    float* qs = sm;
    float* ks = sm + 64*PAD;
    float* vs = sm + 2*64*PAD;
    float* rowm = sm + 3*64*PAD;
    float* rowl = rowm + 64;
    float* rowf = rowl + 64;
    float* ps = qs;

    const float* Q = g_q[which];
    const float* K = g_k[which];
    const float* V = g_v[which];
    float* O = g_o[which];
    int bh = blockIdx.y, q0 = blockIdx.x * 64;
    int tid = threadIdx.x;
    int wid = tid >> 5, lane = tid & 31;
    int wm = wid >> 1, wn = wid & 1;
    int g = lane >> 2, t = lane & 3;
    int fr0 = wm*16 + g;

    {
        int r = tid >> 2, c0 = (tid & 3) * 16;
        const float* src = Q + ((size_t)bh*NS + q0 + r)*ND + c0;
        float* dst = qs + r*PAD + c0;
        #pragma unroll
        for (int i = 0; i < 4; i++) {
            float4 v4 = *(const float4*)(src + i*4);
            dst[i*4+0]=tf32f(v4.x); dst[i*4+1]=tf32f(v4.y);
            dst[i*4+2]=tf32f(v4.z); dst[i*4+3]=tf32f(v4.w);
        }
    }
    if (tid < 64) { rowm[tid] = -1e30f; rowl[tid] = 0.f; }
    __syncthreads();

    unsigned qf[8][4];
    #pragma unroll
    for (int kc = 0; kc < 8; kc++) {
        const float* base = qs + fr0*PAD + kc*8 + t;
        qf[kc][0] = __float_as_uint(base[0]);
        qf[kc][1] = __float_as_uint(base[8*PAD]);
        qf[kc][2] = __float_as_uint(base[4]);
        qf[kc][3] = __float_as_uint(base[8*PAD+4]);
    }
    __syncthreads();

    float of[4][4] = {};
    for (int j0 = 0; j0 < NS; j0 += 64) {
        {
            int r = tid >> 2, c0 = (tid & 3) * 16;
            const float* ksrc = K + ((size_t)bh*NS + j0 + r)*ND + c0;
            const float* vsrc = V + ((size_t)bh*NS + j0 + r)*ND + c0;
            float* kd = ks + r*PAD + c0;
            float* vd = vs + r*PAD + c0;
            #pragma unroll
            for (int i = 0; i < 4; i++) {
                float4 kv = *(const float4*)(ksrc + i*4);
                float4 vv = *(const float4*)(vsrc + i*4);
                kd[i*4+0]=tf32f(kv.x); kd[i*4+1]=tf32f(kv.y);
                kd[i*4+2]=tf32f(kv.z); kd[i*4+3]=tf32f(kv.w);
                vd[i*4+0]=tf32f(vv.x); vd[i*4+1]=tf32f(vv.y);
                vd[i*4+2]=tf32f(vv.z); vd[i*4+3]=tf32f(vv.w);
            }
        }
        __syncthreads();

        float cf[4][4] = {};
        #pragma unroll
        for (int nt = 0; nt < 4; nt++) {
            int nb = wn*32 + nt*8;
            const float* bbase = ks + (nb + g)*PAD;
            #pragma unroll
            for (int kc = 0; kc < 8; kc++) {
                unsigned b0 = __float_as_uint(bbase[kc*8 + t]);
                unsigned b1 = __float_as_uint(bbase[kc*8 + t + 4]);
                mma_tf32(cf[nt], qf[kc], b0, b1);
            }
        }
        #pragma unroll
        for (int nt = 0; nt < 4; nt++) {
            float* p0 = ps + fr0*PAD + wn*32 + nt*8 + 2*t;
            *(float2*)p0 = make_float2(cf[nt][0], cf[nt][1]);
            *(float2*)(p0 + 8*PAD) = make_float2(cf[nt][2], cf[nt][3]);
        }
        __syncthreads();

        {
            int r = tid >> 2, c0 = (tid & 3) * 16;
            float* prow = ps + r*PAD;
            float mx = -1e30f;
            #pragma unroll
            for (int i = 0; i < 16; i++) mx = fmaxf(mx, prow[c0+i]);
            mx = fmaxf(mx, __shfl_xor_sync(0xffffffffu, mx, 1));
            mx = fmaxf(mx, __shfl_xor_sync(0xffffffffu, mx, 2));
            float mold = rowm[r];
            float mnew = fmaxf(mold, mx);
            float fr = __expf(mold - mnew);
            float l = 0.f;
            #pragma unroll
            for (int i = 0; i < 16; i++) {
                float e = __expf(prow[c0+i] - mnew);
                prow[c0+i] = tf32f(e);
                l += e;
            }
            l += __shfl_xor_sync(0xffffffffu, l, 1);
            l += __shfl_xor_sync(0xffffffffu, l, 2);
            if ((tid & 3) == 0) {
                rowl[r] = rowl[r]*fr + l;
                rowm[r] = mnew;
                rowf[r] = fr;
            }
        }
        __syncthreads();

        float f0 = rowf[fr0], f1 = rowf[fr0 + 8];
        #pragma unroll
        for (int nt = 0; nt < 4; nt++) {
            of[nt][0] *= f0; of[nt][1] *= f0;
            of[nt][2] *= f1; of[nt][3] *= f1;
        }

        #pragma unroll
        for (int kc = 0; kc < 8; kc++) {
            const float* pa = ps + fr0*PAD + kc*8 + t;
            unsigned a[4];
            a[0] = __float_as_uint(pa[0]);
            a[1] = __float_as_uint(pa[8*PAD]);
            a[2] = __float_as_uint(pa[4]);
            a[3] = __float_as_uint(pa[8*PAD+4]);
            #pragma unroll
            for (int nt = 0; nt < 4; nt++) {
                int nb = wn*32 + nt*8;
                unsigned b0 = __float_as_uint(vs[(kc*8 + t)*PAD + nb + g]);
                unsigned b1 = __float_as_uint(vs[(kc*8 + t + 4)*PAD + nb + g]);
                mma_tf32(of[nt], a, b0, b1);
            }
        }
        __syncthreads();
    }

    float il0 = 1.f / rowl[fr0];
    float il1 = 1.f / rowl[fr0 + 8];
    #pragma unroll
    for (int nt = 0; nt < 4; nt++) {
        int col = wn*32 + nt*8 + 2*t;
        float* o0 = O + ((size_t)bh*NS + q0 + fr0)*ND + col;
        float* o1 = O + ((size_t)bh*NS + q0 + fr0 + 8)*ND + col;
        *(float2*)o0 = make_float2(of[nt][0]*il0, of[nt][1]*il0);
        *(float2*)o1 = make_float2(of[nt][2]*il1, of[nt][3]*il1);
    }
}

// ============ out projection + residual (tf32 tensor cores) ============
__global__ void outproj_tf32_kernel(const float* __restrict__ out_w,
                                    const float* __restrict__ out_b, int which) {
    __shared__ __align__(16) float Xs[64*QPA];
    __shared__ __align__(16) float Wsm[64*QPA];
    int bh = blockIdx.y, h = bh & (NH-1), s0 = blockIdx.x*64;
    int tid = threadIdx.x;
    int wid = tid >> 5, lane = tid & 31;
    int wm = wid >> 1, wn = wid & 1;
    int g = lane >> 2, t = lane & 3;
    int fr0 = wm*16 + g;
    int lr = tid >> 4, lc = (tid & 15) * 4;
    const float* xbase = g_o[which] + ((size_t)bh*NS + s0)*ND;
    const float* wsrc  = out_w + (size_t)h*64*64;   // [f][e]
    #pragma unroll
    for (int i = 0; i < 4; i++) {
        int r = lr + i*16;
        float4 x = *(const float4*)(xbase + r*ND + lc);
        float4 w = *(const float4*)(wsrc  + r*64 + lc);
        float* xd = Xs + r*QPA + lc;
        float* wd = Wsm + r*QPA + lc;
        xd[0]=tf32f(x.x); xd[1]=tf32f(x.y); xd[2]=tf32f(x.z); xd[3]=tf32f(x.w);
        wd[0]=tf32f(w.x); wd[1]=tf32f(w.y); wd[2]=tf32f(w.z); wd[3]=tf32f(w.w);
    }
    __syncthreads();
    float acc[4][4] = {};
    #pragma unroll
    for (int kc = 0; kc < 8; kc++) {
        const float* ab = Xs + fr0*QPA + kc*8 + t;
        unsigned a[4];
        a[0]=__float_as_uint(ab[0]);  a[1]=__float_as_uint(ab[8*QPA]);
        a[2]=__float_as_uint(ab[4]);  a[3]=__float_as_uint(ab[8*QPA+4]);
        #pragma unroll
        for (int nt = 0; nt < 4; nt++) {
            const float* bb = Wsm + (wn*32 + nt*8 + g)*QPA + kc*8 + t;
            mma_tf32(acc[nt], a, __float_as_uint(bb[0]), __float_as_uint(bb[4]));
        }
    }
    const float* resid = g_c[which];
    int off = which * 64;
    #pragma unroll
    for (int nt = 0; nt < 4; nt++) {
        int c = wn*32 + nt*8 + 2*t;
        float bx = out_b[h*64+c], by = out_b[h*64+c+1];
        int s0r = s0 + fr0, s1r = s0 + fr0 + 8;
        const float* r0 = resid + ((size_t)bh*NS + s0r)*ND + c;
        const float* r1 = resid + ((size_t)bh*NS + s1r)*ND + c;
        float* d0 = g_comb + ((size_t)bh*NS + s0r)*128 + off + c;
        float* d1 = g_comb + ((size_t)bh*NS + s1r)*128 + off + c;
        *(float2*)d0 = make_float2(acc[nt][0]+bx+r0[0], acc[nt][1]+by+r0[1]);
        *(float2*)d1 = make_float2(acc[nt][2]+bx+r1[0], acc[nt][3]+by+r1[1]);
    }
}

// ---------------- final LN over concat dim (128) ----------------
__global__ void final_ln_kernel(const float* __restrict__ hg, const float* __restrict__ hb,
                                float* __restrict__ out) {
    int row = blockIdx.x * 8 + (threadIdx.x >> 5);
    int lane = threadIdx.x & 31;
    const float* x = g_comb + (size_t)row * 128;
    float v[4], sum = 0.f;
    #pragma unroll
    for (int i=0;i<4;i++){ v[i] = x[lane + i*32]; sum += v[i]; }
    #pragma unroll
    for (int o = 16; o > 0; o >>= 1) sum += __shfl_xor_sync(0xffffffffu, sum, o);
    float mu = sum * (1.f/128.f);
    float sq = 0.f;
    #pragma unroll
    for (int i=0;i<4;i++){ float d = v[i]-mu; sq += d*d; }
    #pragma unroll
    for (int o = 16; o > 0; o >>= 1) sq += __shfl_xor_sync(0xffffffffu, sq, o);
    float rstd = rsqrtf(sq*(1.f/128.f) + 1e-5f);
    int h = (row >> 9) & 15;
    #pragma unroll
    for (int i=0;i<4;i++){
        int c = lane + i*32;
        out[(size_t)row*128 + c] = (v[i]-mu)*rstd*hg[h*128+c] + hb[h*128+c];
    }
}

// ---------------- launch ----------------
extern "C" void kernel_launch(void* const* d_in, const int* in_sizes, int n_in,
                              void* d_out, int out_size) {
    const float* image     = (const float*)d_in[0];
    const float* text      = (const float*)d_in[1];
    const float* img_w     = (const float*)d_in[2];
    const float* img_b     = (const float*)d_in[3];
    const float* img_g     = (const float*)d_in[4];
    const float* img_lb    = (const float*)d_in[5];
    const float* txt_w     = (const float*)d_in[6];
    const float* txt_b     = (const float*)d_in[7];
    const float* txt_g     = (const float*)d_in[8];
    const float* txt_lb    = (const float*)d_in[9];
    const float* i2t_in_w  = (const float*)d_in[10];
    const float* i2t_in_b  = (const float*)d_in[11];
    const float* i2t_out_w = (const float*)d_in[12];
    const float* i2t_out_b = (const float*)d_in[13];
    const float* t2i_in_w  = (const float*)d_in[14];
    const float* t2i_in_b  = (const float*)d_in[15];
    const float* t2i_out_w = (const float*)d_in[16];
    const float* t2i_out_b = (const float*)d_in[17];
    const float* hn_g      = (const float*)d_in[18];
    const float* hn_b      = (const float*)d_in[19];
    float* out = (float*)d_out;

    const int ATTN_SMEM = (3*64*PAD + 3*64) * 4;     // 59136 B
    const int QKV_SMEM  = 3*64*QPA*4;                // 52224 B
    static int attrs_set = 0;
    if (!attrs_set) {
        cudaFuncSetAttribute(attn_kernel, cudaFuncAttributeMaxDynamicSharedMemorySize, ATTN_SMEM);
        cudaFuncSetAttribute(qkv_tf32_kernel, cudaFuncAttributeMaxDynamicSharedMemorySize, QKV_SMEM);
        attrs_set = 1;
    }

    dim3 thr(256);
    gemm_tf32_kernel<<<dim3(8,64), thr>>>(image, img_w, img_b, 768, 0);
    gemm_tf32_kernel<<<dim3(8,64), thr>>>(text,  txt_w, txt_b, 512, 1);
    ln_l2_kernel<<<8192, thr>>>(img_g, img_lb, 0);
    ln_l2_kernel<<<8192, thr>>>(txt_g, txt_lb, 1);
    qkv_tf32_kernel<<<dim3(8,256), thr, QKV_SMEM>>>(i2t_in_w, i2t_in_b, 0);
    qkv_tf32_kernel<<<dim3(8,256), thr, QKV_SMEM>>>(t2i_in_w, t2i_in_b, 1);
    attn_kernel<<<dim3(8,256), thr, ATTN_SMEM>>>(0);
    attn_kernel<<<dim3(8,256), thr, ATTN_SMEM>>>(1);
    outproj_tf32_kernel<<<dim3(8,256), thr>>>(i2t_out_w, i2t_out_b, 0);
    outproj_tf32_kernel<<<dim3(8,256), thr>>>(t2i_out_w, t2i_out_b, 1);
    final_ln_kernel<<<16384, thr>>>(hn_g, hn_b, out);
}